// round 1
// baseline (speedup 1.0000x reference)
#include <cuda_runtime.h>
#include <math.h>

#define MAX_B 64
#define MAX_P 2048
#define BLK   128
#define PPT   2      // pred points per thread
#define MAX_GX 16

struct Samp {
    float Rp[9];
    float Rg[9];
    int   cls;
    int   use_closest;
    int   valid;
};

__device__ Samp  g_samp[MAX_B];
__device__ float g_part[MAX_B * MAX_GX];

__device__ __forceinline__ void quat2rot(float w, float x, float y, float z, float* R) {
    R[0] = 1.f - 2.f * (y * y + z * z);
    R[1] = 2.f * (x * y - z * w);
    R[2] = 2.f * (x * z + y * w);
    R[3] = 2.f * (x * y + z * w);
    R[4] = 1.f - 2.f * (x * x + z * z);
    R[5] = 2.f * (y * z - x * w);
    R[6] = 2.f * (x * z - y * w);
    R[7] = 2.f * (y * z + x * w);
    R[8] = 1.f - 2.f * (x * x + y * y);
}

__device__ __forceinline__ float sl1(float v) {
    float a = fabsf(v);
    return (a < 1.f) ? 0.5f * v * v : a - 0.5f;
}

__global__ void pm_setup(const float* __restrict__ pred,
                         const float* __restrict__ tgt,
                         const float* __restrict__ w,
                         const float* __restrict__ sym,
                         int B, int C) {
    int b = blockIdx.x * blockDim.x + threadIdx.x;
    if (b >= B) return;

    // first class with weight slot-0 > 0 (matches argmax(wsel>0)); valid if any
    int cls = 0, valid = 0;
    for (int c = 0; c < C; ++c) {
        if (w[(b * C + c) * 4] > 0.f) { cls = c; valid = 1; break; }
    }

    Samp s;
    const float* qp = pred + (size_t)(b * C + cls) * 4;
    const float* qg = tgt  + (size_t)(b * C + cls) * 4;
    float pw = qp[0], px = qp[1], py = qp[2], pz = qp[3];
    float gw = qg[0], gx = qg[1], gy = qg[2], gz = qg[3];
    quat2rot(pw, px, py, pz, s.Rp);
    quat2rot(gw, gx, gy, gz, s.Rg);

    float dot = fabsf(pw * gw + px * gx + py * gy + pz * gz);
    dot = fminf(fmaxf(dot, 0.f), 1.f);
    float ang = 2.f * acosf(dot) * (180.f / 3.14159265358979323846f);

    s.cls = cls;
    s.valid = valid;
    s.use_closest = (sym[cls] > 0.f && ang > 15.f) ? 1 : 0;
    g_samp[b] = s;
}

__global__ void pm_main(const float* __restrict__ points, int P, int GX) {
    __shared__ float sgx[MAX_P];
    __shared__ float sgy[MAX_P];
    __shared__ float sgz[MAX_P];
    __shared__ float shg[MAX_P];
    __shared__ float red[BLK];

    const int b   = blockIdx.y;
    const int tid = threadIdx.x;
    Samp s = g_samp[b];

    float lsum = 0.f;

    if (s.valid) {
        const float* pt = points + (size_t)s.cls * P * 3;

        // cooperatively rotate the full gt cloud into SMEM + half squared norms
        for (int q = tid; q < P; q += BLK) {
            float x = pt[3 * q + 0];
            float y = pt[3 * q + 1];
            float z = pt[3 * q + 2];
            float gx = s.Rg[0] * x + s.Rg[1] * y + s.Rg[2] * z;
            float gy = s.Rg[3] * x + s.Rg[4] * y + s.Rg[5] * z;
            float gz = s.Rg[6] * x + s.Rg[7] * y + s.Rg[8] * z;
            sgx[q] = gx;
            sgy[q] = gy;
            sgz[q] = gz;
            shg[q] = 0.5f * (gx * gx + gy * gy + gz * gz);
        }
        __syncthreads();

        // each thread owns PPT pred points
        float px[PPT], py[PPT], pz[PPT];
        int   pidx[PPT];
#pragma unroll
        for (int j = 0; j < PPT; ++j) {
            int p = blockIdx.x * (BLK * PPT) + j * BLK + tid;
            pidx[j] = p;
            px[j] = py[j] = pz[j] = 0.f;
            if (p < P) {
                float x = pt[3 * p + 0];
                float y = pt[3 * p + 1];
                float z = pt[3 * p + 2];
                px[j] = s.Rp[0] * x + s.Rp[1] * y + s.Rp[2] * z;
                py[j] = s.Rp[3] * x + s.Rp[4] * y + s.Rp[5] * z;
                pz[j] = s.Rp[6] * x + s.Rp[7] * y + s.Rp[8] * z;
            }
        }

        if (s.use_closest) {
            // argmin_q (0.5|g_q|^2 - p . g_q)  ==  argmin_q |p - g_q|^2
            float best[PPT];
            int   bi[PPT];
#pragma unroll
            for (int j = 0; j < PPT; ++j) { best[j] = 3.4e38f; bi[j] = 0; }

#pragma unroll 4
            for (int q = 0; q < P; ++q) {
                float gx = sgx[q];
                float gy = sgy[q];
                float gz = sgz[q];
                float hg = shg[q];
#pragma unroll
                for (int j = 0; j < PPT; ++j) {
                    float t = hg - px[j] * gx - py[j] * gy - pz[j] * gz;
                    if (t < best[j]) { best[j] = t; bi[j] = q; }
                }
            }
#pragma unroll
            for (int j = 0; j < PPT; ++j) {
                if (pidx[j] < P) {
                    int k = bi[j];
                    float dx = px[j] - sgx[k];
                    float dy = py[j] - sgy[k];
                    float dz = pz[j] - sgz[k];
                    lsum += sl1(dx) + sl1(dy) + sl1(dz);
                }
            }
        } else {
#pragma unroll
            for (int j = 0; j < PPT; ++j) {
                if (pidx[j] < P) {
                    int k = pidx[j];
                    float dx = px[j] - sgx[k];
                    float dy = py[j] - sgy[k];
                    float dz = pz[j] - sgz[k];
                    lsum += sl1(dx) + sl1(dy) + sl1(dz);
                }
            }
        }
        __syncthreads();
    }

    // deterministic block tree-reduce
    red[tid] = lsum;
    __syncthreads();
#pragma unroll
    for (int st = BLK / 2; st > 0; st >>= 1) {
        if (tid < st) red[tid] += red[tid + st];
        __syncthreads();
    }
    if (tid == 0) g_part[b * GX + blockIdx.x] = red[0];
}

__global__ void pm_final(float* __restrict__ out, int nparts, float inv) {
    __shared__ float red[256];
    float v = 0.f;
    for (int i = threadIdx.x; i < nparts; i += 256) v += g_part[i];
    red[threadIdx.x] = v;
    __syncthreads();
#pragma unroll
    for (int st = 128; st > 0; st >>= 1) {
        if (threadIdx.x < st) red[threadIdx.x] += red[threadIdx.x + st];
        __syncthreads();
    }
    if (threadIdx.x == 0) out[0] = red[0] * inv;
}

extern "C" void kernel_launch(void* const* d_in, const int* in_sizes, int n_in,
                              void* d_out, int out_size) {
    const float* pred = (const float*)d_in[0];
    const float* tgt  = (const float*)d_in[1];
    const float* w    = (const float*)d_in[2];
    const float* pts  = (const float*)d_in[3];
    const float* sym  = (const float*)d_in[4];

    int C = in_sizes[4];
    int B = in_sizes[0] / (4 * C);
    int P = in_sizes[3] / (3 * C);
    int GX = (P + BLK * PPT - 1) / (BLK * PPT);

    pm_setup<<<1, MAX_B>>>(pred, tgt, w, sym, B, C);

    dim3 grid(GX, B);
    pm_main<<<grid, BLK>>>(pts, P, GX);

    pm_final<<<1, 256>>>((float*)d_out, B * GX, 1.f / (float)(B * P));
}

// round 2
// speedup vs baseline: 1.4110x; 1.4110x over previous
#include <cuda_runtime.h>
#include <math.h>

#define BLK      128
#define MAX_P    2048
#define NBLOCKS  304
#define MAX_ITEMS 4096

// cos(7.5 degrees): ang > 15deg  <=>  |dot| < cos(7.5deg)
#define COS_HALF_HARD 0.9914448613738104f

__device__ unsigned g_ctr  = 0;
__device__ unsigned g_done = 0;
__device__ float    g_part[MAX_ITEMS];

__device__ __forceinline__ float sl1(float v) {
    float a = fabsf(v);
    return (a < 1.f) ? 0.5f * v * v : a - 0.5f;
}

__device__ __forceinline__ void quat2rot(float w, float x, float y, float z, float* R) {
    R[0] = 1.f - 2.f * (y * y + z * z);
    R[1] = 2.f * (x * y - z * w);
    R[2] = 2.f * (x * z + y * w);
    R[3] = 2.f * (x * y + z * w);
    R[4] = 1.f - 2.f * (x * x + z * z);
    R[5] = 2.f * (y * z - x * w);
    R[6] = 2.f * (x * z - y * w);
    R[7] = 2.f * (y * z + x * w);
    R[8] = 1.f - 2.f * (x * x + y * y);
}

__global__ void __launch_bounds__(BLK, 2)
pm_fused(const float* __restrict__ pred,
         const float* __restrict__ tgt,
         const float* __restrict__ w,
         const float* __restrict__ sym,
         const float* __restrict__ points,
         int B, int C, int P, int CHUNKS, int NITEMS,
         float inv, float* __restrict__ out) {
    __shared__ float4   sg[MAX_P];   // rotated gt cloud: (gx, gy, gz, 0.5*|g|^2)
    __shared__ float    red[BLK];
    __shared__ unsigned s_item;

    const int tid = threadIdx.x;

    // per-sample setup, cached across items that hit the same sample
    int   prev_b = -1;     // sample whose setup is in registers
    int   fill_b = -1;     // sample whose gt cloud is in SMEM
    float Rp[9], Rg[9];
    int   cls = 0, valid = 0, use_closest = 0;

    for (;;) {
        if (tid == 0) s_item = atomicAdd(&g_ctr, 1u);
        __syncthreads();               // also guarantees previous item fully done
        unsigned it = s_item;
        if (it >= (unsigned)NITEMS) break;

        const int b     = (int)(it / (unsigned)CHUNKS);
        const int chunk = (int)(it % (unsigned)CHUNKS);

        if (b != prev_b) {
            prev_b = b;
            cls = 0; valid = 0;
            for (int c = 0; c < C; ++c) {
                if (__ldg(&w[(size_t)(b * C + c) * 4]) > 0.f) { cls = c; valid = 1; break; }
            }
            const float* qp = pred + (size_t)(b * C + cls) * 4;
            const float* qg = tgt  + (size_t)(b * C + cls) * 4;
            float pw = __ldg(qp + 0), px = __ldg(qp + 1), py = __ldg(qp + 2), pz = __ldg(qp + 3);
            float gw = __ldg(qg + 0), gx = __ldg(qg + 1), gy = __ldg(qg + 2), gz = __ldg(qg + 3);
            quat2rot(pw, px, py, pz, Rp);
            quat2rot(gw, gx, gy, gz, Rg);
            float dot = fabsf(pw * gw + px * gx + py * gy + pz * gz);
            use_closest = (__ldg(&sym[cls]) > 0.f) && (dot < COS_HALF_HARD);
        }

        float lsum = 0.f;

        if (valid) {
            const float* pt = points + (size_t)cls * P * 3;
            const int    p  = chunk * BLK + tid;
            const bool   inb = (p < P);

            float px = 0.f, py = 0.f, pz = 0.f, x = 0.f, y = 0.f, z = 0.f;
            if (inb) {
                x = __ldg(&pt[3 * p + 0]);
                y = __ldg(&pt[3 * p + 1]);
                z = __ldg(&pt[3 * p + 2]);
                px = Rp[0] * x + Rp[1] * y + Rp[2] * z;
                py = Rp[3] * x + Rp[4] * y + Rp[5] * z;
                pz = Rp[6] * x + Rp[7] * y + Rp[8] * z;
            }

            if (use_closest) {
                if (fill_b != b) {
                    // claim barrier above guarantees no one still reads old sg
                    for (int q = tid; q < P; q += BLK) {
                        float qx = __ldg(&pt[3 * q + 0]);
                        float qy = __ldg(&pt[3 * q + 1]);
                        float qz = __ldg(&pt[3 * q + 2]);
                        float gx = Rg[0] * qx + Rg[1] * qy + Rg[2] * qz;
                        float gy = Rg[3] * qx + Rg[4] * qy + Rg[5] * qz;
                        float gz = Rg[6] * qx + Rg[7] * qy + Rg[8] * qz;
                        sg[q] = make_float4(gx, gy, gz, 0.5f * (gx * gx + gy * gy + gz * gz));
                    }
                    fill_b = b;
                }
                __syncthreads();

                // argmin_q (0.5|g|^2 - p.g); index packed into low 11 mantissa bits.
                // 3 FFMA (fma pipe) + LOP3 + FMNMX (alu pipe) per pair.
                float best = __uint_as_float(0x7F7FFFFFu);
#pragma unroll 8
                for (int q = 0; q < P; ++q) {
                    float4 g = sg[q];
                    float t = fmaf(-px, g.x, g.w);
                    t = fmaf(-py, g.y, t);
                    t = fmaf(-pz, g.z, t);
                    unsigned tb = (__float_as_uint(t) & 0xFFFFF800u) | (unsigned)q;
                    best = fminf(best, __uint_as_float(tb));
                }
                if (inb) {
                    int k = (int)(__float_as_uint(best) & 0x7FFu);
                    float4 g = sg[k];
                    lsum = sl1(px - g.x) + sl1(py - g.y) + sl1(pz - g.z);
                }
            } else {
                if (inb) {
                    float gx = Rg[0] * x + Rg[1] * y + Rg[2] * z;
                    float gy = Rg[3] * x + Rg[4] * y + Rg[5] * z;
                    float gz = Rg[6] * x + Rg[7] * y + Rg[8] * z;
                    lsum = sl1(px - gx) + sl1(py - gy) + sl1(pz - gz);
                }
            }
        }

        // deterministic per-item block reduce into fixed slot g_part[it]
        red[tid] = lsum;
        __syncthreads();
#pragma unroll
        for (int st = BLK / 2; st > 0; st >>= 1) {
            if (tid < st) red[tid] += red[tid + st];
            __syncthreads();
        }
        if (tid == 0) g_part[it] = red[0];
    }

    // last-block final reduction (fixed order -> deterministic)
    __syncthreads();
    if (tid == 0) {
        __threadfence();
        unsigned d = atomicAdd(&g_done, 1u);
        s_item = (d == gridDim.x - 1) ? 1u : 0u;
    }
    __syncthreads();
    if (s_item) {
        __threadfence();
        float v = 0.f;
        for (int i = tid; i < NITEMS; i += BLK) v += g_part[i];
        red[tid] = v;
        __syncthreads();
#pragma unroll
        for (int st = BLK / 2; st > 0; st >>= 1) {
            if (tid < st) red[tid] += red[tid + st];
            __syncthreads();
        }
        if (tid == 0) {
            out[0] = red[0] * inv;
            g_ctr  = 0;
            g_done = 0;
        }
    }
}

extern "C" void kernel_launch(void* const* d_in, const int* in_sizes, int n_in,
                              void* d_out, int out_size) {
    const float* pred = (const float*)d_in[0];
    const float* tgt  = (const float*)d_in[1];
    const float* w    = (const float*)d_in[2];
    const float* pts  = (const float*)d_in[3];
    const float* sym  = (const float*)d_in[4];

    int C = in_sizes[4];
    int B = in_sizes[0] / (4 * C);
    int P = in_sizes[3] / (3 * C);
    int CHUNKS = (P + BLK - 1) / BLK;
    int NITEMS = B * CHUNKS;

    pm_fused<<<NBLOCKS, BLK>>>(pred, tgt, w, sym, pts,
                               B, C, P, CHUNKS, NITEMS,
                               1.f / (float)(B * P), (float*)d_out);
}

// round 3
// speedup vs baseline: 1.6045x; 1.1371x over previous
#include <cuda_runtime.h>
#include <math.h>

#define BLK      256
#define NW       8          // warps per block
#define CHUNK    128        // pred points per item
#define MAX_P    2048
#define NBLOCKS  304
#define MAX_ITEMS 4096

// cos(7.5 degrees): ang > 15deg  <=>  |dot| < cos(7.5deg)
#define COS_HALF_HARD 0.9914448613738104f

__device__ unsigned g_ctr  = 0;
__device__ unsigned g_done = 0;
__device__ float    g_part[MAX_ITEMS];

__device__ __forceinline__ float sl1(float v) {
    float a = fabsf(v);
    return (a < 1.f) ? 0.5f * v * v : a - 0.5f;
}

__device__ __forceinline__ void quat2rot(float w, float x, float y, float z, float* R) {
    R[0] = 1.f - 2.f * (y * y + z * z);
    R[1] = 2.f * (x * y - z * w);
    R[2] = 2.f * (x * z + y * w);
    R[3] = 2.f * (x * y + z * w);
    R[4] = 1.f - 2.f * (x * x + z * z);
    R[5] = 2.f * (y * z - x * w);
    R[6] = 2.f * (x * z - y * w);
    R[7] = 2.f * (y * z + x * w);
    R[8] = 1.f - 2.f * (x * x + y * y);
}

__global__ void __launch_bounds__(BLK, 2)
pm_fused(const float* __restrict__ pred,
         const float* __restrict__ tgt,
         const float* __restrict__ w,
         const float* __restrict__ sym,
         const float* __restrict__ points,
         int B, int C, int P, int CHUNKS, int NITEMS,
         float inv, float* __restrict__ out) {
    __shared__ float4   sg[MAX_P];           // rotated gt cloud: (gx,gy,gz, 0.5|g|^2)
    __shared__ float    sbest[NW * CHUNK];   // per-warp partial argmins (packed)
    __shared__ float    red[BLK];
    __shared__ unsigned s_item;

    const int tid  = threadIdx.x;
    const int wid  = tid >> 5;
    const int lane = tid & 31;

    int   prev_b = -1;   // sample whose setup is in registers
    int   fill_b = -1;   // sample whose gt cloud is in SMEM
    float Rp[9], Rg[9];
    int   cls = 0, valid = 0, use_closest = 0;

    const int QW = (P + NW - 1) / NW;        // q-range per warp

    for (;;) {
        if (tid == 0) s_item = atomicAdd(&g_ctr, 1u);
        __syncthreads();                     // claim barrier; protects sg/sbest reuse
        unsigned it = s_item;
        if (it >= (unsigned)NITEMS) break;

        const int b     = (int)(it / (unsigned)CHUNKS);
        const int chunk = (int)(it % (unsigned)CHUNKS);

        if (b != prev_b) {                   // uniform across block
            prev_b = b;
            cls = 0; valid = 0;
            for (int c = 0; c < C; ++c) {
                if (__ldg(&w[(size_t)(b * C + c) * 4]) > 0.f) { cls = c; valid = 1; break; }
            }
            const float* qp = pred + (size_t)(b * C + cls) * 4;
            const float* qg = tgt  + (size_t)(b * C + cls) * 4;
            float pw = __ldg(qp + 0), px_ = __ldg(qp + 1), py_ = __ldg(qp + 2), pz_ = __ldg(qp + 3);
            float gw = __ldg(qg + 0), gx_ = __ldg(qg + 1), gy_ = __ldg(qg + 2), gz_ = __ldg(qg + 3);
            quat2rot(pw, px_, py_, pz_, Rp);
            quat2rot(gw, gx_, gy_, gz_, Rg);
            float dot = fabsf(pw * gw + px_ * gx_ + py_ * gy_ + pz_ * gz_);
            use_closest = (__ldg(&sym[cls]) > 0.f) && (dot < COS_HALF_HARD);
        }

        float lsum = 0.f;

        if (valid) {
            const float* pt    = points + (size_t)cls * P * 3;
            const int    pbase = chunk * CHUNK;

            if (use_closest) {
                // every warp holds rotated pred points {pbase + lane + 32j}
                float px[4], py[4], pz[4];
#pragma unroll
                for (int j = 0; j < 4; ++j) {
                    int p = pbase + lane + 32 * j;
                    px[j] = py[j] = pz[j] = 0.f;
                    if (p < P) {
                        float x = __ldg(&pt[3 * p + 0]);
                        float y = __ldg(&pt[3 * p + 1]);
                        float z = __ldg(&pt[3 * p + 2]);
                        px[j] = Rp[0] * x + Rp[1] * y + Rp[2] * z;
                        py[j] = Rp[3] * x + Rp[4] * y + Rp[5] * z;
                        pz[j] = Rp[6] * x + Rp[7] * y + Rp[8] * z;
                    }
                }

                if (fill_b != b) {
                    for (int q = tid; q < P; q += BLK) {
                        float qx = __ldg(&pt[3 * q + 0]);
                        float qy = __ldg(&pt[3 * q + 1]);
                        float qz = __ldg(&pt[3 * q + 2]);
                        float gx = Rg[0] * qx + Rg[1] * qy + Rg[2] * qz;
                        float gy = Rg[3] * qx + Rg[4] * qy + Rg[5] * qz;
                        float gz = Rg[6] * qx + Rg[7] * qy + Rg[8] * qz;
                        sg[q] = make_float4(gx, gy, gz, 0.5f * (gx * gx + gy * gy + gz * gz));
                    }
                    fill_b = b;
                }
                __syncthreads();

                // warp wid scans its q slice; 4 independent min-chains per lane
                float best[4];
#pragma unroll
                for (int j = 0; j < 4; ++j) best[j] = __uint_as_float(0x7F7FFFFFu);

                const int q0   = wid * QW;
                const int qend = min(q0 + QW, P);
#pragma unroll 4
                for (int q = q0; q < qend; ++q) {
                    float4 g = sg[q];
#pragma unroll
                    for (int j = 0; j < 4; ++j) {
                        float t = fmaf(-px[j], g.x, g.w);
                        t = fmaf(-py[j], g.y, t);
                        t = fmaf(-pz[j], g.z, t);
                        unsigned tb = (__float_as_uint(t) & 0xFFFFF800u) | (unsigned)q;
                        best[j] = fminf(best[j], __uint_as_float(tb));
                    }
                }
#pragma unroll
                for (int j = 0; j < 4; ++j)
                    sbest[wid * CHUNK + lane + 32 * j] = best[j];
                __syncthreads();

                // thread t (<128) finalizes pred point pbase+t
                if (tid < CHUNK) {
                    int p = pbase + tid;
                    if (p < P) {
                        float m = sbest[tid];
#pragma unroll
                        for (int ww = 1; ww < NW; ++ww)
                            m = fminf(m, sbest[ww * CHUNK + tid]);
                        int k = (int)(__float_as_uint(m) & 0x7FFu);

                        float x = __ldg(&pt[3 * p + 0]);
                        float y = __ldg(&pt[3 * p + 1]);
                        float z = __ldg(&pt[3 * p + 2]);
                        float ppx = Rp[0] * x + Rp[1] * y + Rp[2] * z;
                        float ppy = Rp[3] * x + Rp[4] * y + Rp[5] * z;
                        float ppz = Rp[6] * x + Rp[7] * y + Rp[8] * z;
                        float4 g = sg[k];
                        lsum = sl1(ppx - g.x) + sl1(ppy - g.y) + sl1(ppz - g.z);
                    }
                }
            } else {
                if (tid < CHUNK) {
                    int p = pbase + tid;
                    if (p < P) {
                        float x = __ldg(&pt[3 * p + 0]);
                        float y = __ldg(&pt[3 * p + 1]);
                        float z = __ldg(&pt[3 * p + 2]);
                        float ppx = Rp[0] * x + Rp[1] * y + Rp[2] * z;
                        float ppy = Rp[3] * x + Rp[4] * y + Rp[5] * z;
                        float ppz = Rp[6] * x + Rp[7] * y + Rp[8] * z;
                        float gx = Rg[0] * x + Rg[1] * y + Rg[2] * z;
                        float gy = Rg[3] * x + Rg[4] * y + Rg[5] * z;
                        float gz = Rg[6] * x + Rg[7] * y + Rg[8] * z;
                        lsum = sl1(ppx - gx) + sl1(ppy - gy) + sl1(ppz - gz);
                    }
                }
            }
        }

        // deterministic per-item block reduce into fixed slot g_part[it]
        red[tid] = lsum;
        __syncthreads();
#pragma unroll
        for (int st = BLK / 2; st > 0; st >>= 1) {
            if (tid < st) red[tid] += red[tid + st];
            __syncthreads();
        }
        if (tid == 0) g_part[it] = red[0];
    }

    // last-block final reduction (fixed order -> deterministic)
    __syncthreads();
    if (tid == 0) {
        __threadfence();
        unsigned d = atomicAdd(&g_done, 1u);
        s_item = (d == gridDim.x - 1) ? 1u : 0u;
    }
    __syncthreads();
    if (s_item) {
        __threadfence();
        float v = 0.f;
        for (int i = tid; i < NITEMS; i += BLK) v += g_part[i];
        red[tid] = v;
        __syncthreads();
#pragma unroll
        for (int st = BLK / 2; st > 0; st >>= 1) {
            if (tid < st) red[tid] += red[tid + st];
            __syncthreads();
        }
        if (tid == 0) {
            out[0] = red[0] * inv;
            g_ctr  = 0;
            g_done = 0;
        }
    }
}

extern "C" void kernel_launch(void* const* d_in, const int* in_sizes, int n_in,
                              void* d_out, int out_size) {
    const float* pred = (const float*)d_in[0];
    const float* tgt  = (const float*)d_in[1];
    const float* w    = (const float*)d_in[2];
    const float* pts  = (const float*)d_in[3];
    const float* sym  = (const float*)d_in[4];

    int C = in_sizes[4];
    int B = in_sizes[0] / (4 * C);
    int P = in_sizes[3] / (3 * C);
    int CHUNKS = (P + CHUNK - 1) / CHUNK;
    int NITEMS = B * CHUNKS;

    pm_fused<<<NBLOCKS, BLK>>>(pred, tgt, w, sym, pts,
                               B, C, P, CHUNKS, NITEMS,
                               1.f / (float)(B * P), (float*)d_out);
}

// round 4
// speedup vs baseline: 1.8311x; 1.1412x over previous
#include <cuda_runtime.h>
#include <math.h>

#define BLK      256
#define NW       8          // warps per block
#define CHUNK    128        // pred points per item
#define MAX_P    2048
#define NBLOCKS  304
#define MAX_ITEMS 4096

// cos(7.5 degrees): ang > 15deg  <=>  |dot| < cos(7.5deg)
#define COS_HALF_HARD 0.9914448613738104f

__device__ unsigned g_ctr  = 0;
__device__ unsigned g_done = 0;
__device__ float    g_part[MAX_ITEMS];

__device__ __forceinline__ float sl1(float v) {
    float a = fabsf(v);
    return (a < 1.f) ? 0.5f * v * v : a - 0.5f;
}

__device__ __forceinline__ void quat2rot(float w, float x, float y, float z, float* R) {
    R[0] = 1.f - 2.f * (y * y + z * z);
    R[1] = 2.f * (x * y - z * w);
    R[2] = 2.f * (x * z + y * w);
    R[3] = 2.f * (x * y + z * w);
    R[4] = 1.f - 2.f * (x * x + z * z);
    R[5] = 2.f * (y * z - x * w);
    R[6] = 2.f * (x * z - y * w);
    R[7] = 2.f * (y * z + x * w);
    R[8] = 1.f - 2.f * (x * x + y * y);
}

// Blackwell packed f32x2 FMA (SASS FFMA2) — only reachable via PTX.
__device__ __forceinline__ unsigned long long ffma2(unsigned long long a,
                                                    unsigned long long b,
                                                    unsigned long long c) {
    unsigned long long d;
    asm("fma.rn.f32x2 %0, %1, %2, %3;" : "=l"(d) : "l"(a), "l"(b), "l"(c));
    return d;
}

__device__ __forceinline__ unsigned long long pack2(float lo, float hi) {
    unsigned long long d;
    asm("mov.b64 %0, {%1, %2};" : "=l"(d)
        : "r"(__float_as_uint(lo)), "r"(__float_as_uint(hi)));
    return d;
}

__device__ __forceinline__ void unpack2(unsigned long long v,
                                        unsigned& lo, unsigned& hi) {
    asm("mov.b64 {%0, %1}, %2;" : "=r"(lo), "=r"(hi) : "l"(v));
}

__global__ void __launch_bounds__(BLK, 2)
pm_fused(const float* __restrict__ pred,
         const float* __restrict__ tgt,
         const float* __restrict__ w,
         const float* __restrict__ sym,
         const float* __restrict__ points,
         int B, int C, int P, int CHUNKS, int NITEMS,
         float inv, float* __restrict__ out) {
    // pair-transposed gt cloud: sg2[2i]   = {gx_q0, gx_q1, gy_q0, gy_q1}
    //                           sg2[2i+1] = {gz_q0, gz_q1, hw_q0, hw_q1}   (q0=2i)
    __shared__ float4   sg2[MAX_P];
    __shared__ float    sbest[NW * CHUNK];   // per-warp packed argmin partials
    __shared__ float    sred[NW];
    __shared__ unsigned s_item;

    const int tid  = threadIdx.x;
    const int wid  = tid >> 5;
    const int lane = tid & 31;

    int   prev_b = -1;   // sample whose setup is in registers
    int   fill_b = -1;   // sample whose gt cloud is in SMEM
    float Rp[9], Rg[9];
    int   cls = 0, valid = 0, use_closest = 0;

    const int HALF = (P + 1) >> 1;           // q-pairs
    const int PPW  = (HALF + NW - 1) / NW;   // q-pairs per warp

    for (;;) {
        if (tid == 0) s_item = atomicAdd(&g_ctr, 1u);
        __syncthreads();                     // claim barrier; protects sg2/sbest reuse
        unsigned it = s_item;
        if (it >= (unsigned)NITEMS) break;

        const int b     = (int)(it / (unsigned)CHUNKS);
        const int chunk = (int)(it % (unsigned)CHUNKS);

        if (b != prev_b) {                   // uniform across block
            prev_b = b;
            cls = 0; valid = 0;
            for (int c = 0; c < C; ++c) {
                if (__ldg(&w[(size_t)(b * C + c) * 4]) > 0.f) { cls = c; valid = 1; break; }
            }
            const float* qp = pred + (size_t)(b * C + cls) * 4;
            const float* qg = tgt  + (size_t)(b * C + cls) * 4;
            float pw = __ldg(qp + 0), px_ = __ldg(qp + 1), py_ = __ldg(qp + 2), pz_ = __ldg(qp + 3);
            float gw = __ldg(qg + 0), gx_ = __ldg(qg + 1), gy_ = __ldg(qg + 2), gz_ = __ldg(qg + 3);
            quat2rot(pw, px_, py_, pz_, Rp);
            quat2rot(gw, gx_, gy_, gz_, Rg);
            float dot = fabsf(pw * gw + px_ * gx_ + py_ * gy_ + pz_ * gz_);
            use_closest = (__ldg(&sym[cls]) > 0.f) && (dot < COS_HALF_HARD);
        }

        float lsum = 0.f;

        if (valid) {
            const float* pt    = points + (size_t)cls * P * 3;
            const int    pbase = chunk * CHUNK;

            if (use_closest) {
                // --- rotate + broadcast-pack this lane's 4 pred points ---
                unsigned long long npxx[4], npyy[4], npzz[4];
#pragma unroll
                for (int j = 0; j < 4; ++j) {
                    int p = pbase + lane + 32 * j;
                    float ppx = 0.f, ppy = 0.f, ppz = 0.f;
                    if (p < P) {
                        float x = __ldg(&pt[3 * p + 0]);
                        float y = __ldg(&pt[3 * p + 1]);
                        float z = __ldg(&pt[3 * p + 2]);
                        ppx = Rp[0] * x + Rp[1] * y + Rp[2] * z;
                        ppy = Rp[3] * x + Rp[4] * y + Rp[5] * z;
                        ppz = Rp[6] * x + Rp[7] * y + Rp[8] * z;
                    }
                    npxx[j] = pack2(-ppx, -ppx);
                    npyy[j] = pack2(-ppy, -ppy);
                    npzz[j] = pack2(-ppz, -ppz);
                }

                // --- fill pair-transposed gt cloud ---
                if (fill_b != b) {
                    for (int i = tid; i < HALF; i += BLK) {
                        int q0 = 2 * i, q1 = 2 * i + 1;
                        float x0 = __ldg(&pt[3 * q0 + 0]);
                        float y0 = __ldg(&pt[3 * q0 + 1]);
                        float z0 = __ldg(&pt[3 * q0 + 2]);
                        float g0x = Rg[0] * x0 + Rg[1] * y0 + Rg[2] * z0;
                        float g0y = Rg[3] * x0 + Rg[4] * y0 + Rg[5] * z0;
                        float g0z = Rg[6] * x0 + Rg[7] * y0 + Rg[8] * z0;
                        float h0  = 0.5f * (g0x * g0x + g0y * g0y + g0z * g0z);
                        float g1x = 0.f, g1y = 0.f, g1z = 0.f, h1 = 3.0e38f;
                        if (q1 < P) {
                            float x1 = __ldg(&pt[3 * q1 + 0]);
                            float y1 = __ldg(&pt[3 * q1 + 1]);
                            float z1 = __ldg(&pt[3 * q1 + 2]);
                            g1x = Rg[0] * x1 + Rg[1] * y1 + Rg[2] * z1;
                            g1y = Rg[3] * x1 + Rg[4] * y1 + Rg[5] * z1;
                            g1z = Rg[6] * x1 + Rg[7] * y1 + Rg[8] * z1;
                            h1  = 0.5f * (g1x * g1x + g1y * g1y + g1z * g1z);
                        }
                        sg2[2 * i]     = make_float4(g0x, g1x, g0y, g1y);
                        sg2[2 * i + 1] = make_float4(g0z, g1z, h0, h1);
                    }
                    fill_b = b;
                }
                __syncthreads();

                // --- warp scans its q-pair slice; 8 independent fmin chains ---
                float bl[4], bh[4];
#pragma unroll
                for (int j = 0; j < 4; ++j) {
                    bl[j] = __uint_as_float(0x7F7FFFFFu);
                    bh[j] = __uint_as_float(0x7F7FFFFFu);
                }

                const int i0 = wid * PPW;
                const int i1 = min(i0 + PPW, HALF);
                unsigned  q  = (unsigned)(2 * i0);
#pragma unroll 2
                for (int i = i0; i < i1; ++i, q += 2) {
                    float4 va = sg2[2 * i];
                    float4 vb = sg2[2 * i + 1];
                    unsigned long long gxx = pack2(va.x, va.y);
                    unsigned long long gyy = pack2(va.z, va.w);
                    unsigned long long gzz = pack2(vb.x, vb.y);
                    unsigned long long hww = pack2(vb.z, vb.w);
                    unsigned qo = q + 1u;
#pragma unroll
                    for (int j = 0; j < 4; ++j) {
                        unsigned long long t2 = ffma2(npzz[j], gzz, hww);
                        t2 = ffma2(npyy[j], gyy, t2);
                        t2 = ffma2(npxx[j], gxx, t2);
                        unsigned tlo, thi;
                        unpack2(t2, tlo, thi);
                        unsigned klo = (tlo & 0xFFFFF800u) | q;
                        unsigned khi = (thi & 0xFFFFF800u) | qo;
                        bl[j] = fminf(bl[j], __uint_as_float(klo));
                        bh[j] = fminf(bh[j], __uint_as_float(khi));
                    }
                }
#pragma unroll
                for (int j = 0; j < 4; ++j)
                    sbest[wid * CHUNK + lane + 32 * j] = fminf(bl[j], bh[j]);
                __syncthreads();

                // --- thread t (<128) finalizes pred point pbase+t ---
                if (tid < CHUNK) {
                    int p = pbase + tid;
                    if (p < P) {
                        float m = sbest[tid];
#pragma unroll
                        for (int ww = 1; ww < NW; ++ww)
                            m = fminf(m, sbest[ww * CHUNK + tid]);
                        int k = (int)(__float_as_uint(m) & 0x7FFu);

                        float4 A  = sg2[(k >> 1) * 2];
                        float4 Bv = sg2[(k >> 1) * 2 + 1];
                        float gx = (k & 1) ? A.y  : A.x;
                        float gy = (k & 1) ? A.w  : A.z;
                        float gz = (k & 1) ? Bv.y : Bv.x;

                        float x = __ldg(&pt[3 * p + 0]);
                        float y = __ldg(&pt[3 * p + 1]);
                        float z = __ldg(&pt[3 * p + 2]);
                        float ppx = Rp[0] * x + Rp[1] * y + Rp[2] * z;
                        float ppy = Rp[3] * x + Rp[4] * y + Rp[5] * z;
                        float ppz = Rp[6] * x + Rp[7] * y + Rp[8] * z;
                        lsum = sl1(ppx - gx) + sl1(ppy - gy) + sl1(ppz - gz);
                    }
                }
            } else {
                if (tid < CHUNK) {
                    int p = pbase + tid;
                    if (p < P) {
                        float x = __ldg(&pt[3 * p + 0]);
                        float y = __ldg(&pt[3 * p + 1]);
                        float z = __ldg(&pt[3 * p + 2]);
                        float ppx = Rp[0] * x + Rp[1] * y + Rp[2] * z;
                        float ppy = Rp[3] * x + Rp[4] * y + Rp[5] * z;
                        float ppz = Rp[6] * x + Rp[7] * y + Rp[8] * z;
                        float gx = Rg[0] * x + Rg[1] * y + Rg[2] * z;
                        float gy = Rg[3] * x + Rg[4] * y + Rg[5] * z;
                        float gz = Rg[6] * x + Rg[7] * y + Rg[8] * z;
                        lsum = sl1(ppx - gx) + sl1(ppy - gy) + sl1(ppz - gz);
                    }
                }
            }
        }

        // deterministic per-item reduce (shuffle tree + fixed-order warp merge)
#pragma unroll
        for (int off = 16; off > 0; off >>= 1)
            lsum += __shfl_down_sync(0xFFFFFFFFu, lsum, off);
        if (lane == 0) sred[wid] = lsum;
        __syncthreads();
        if (tid == 0) {
            float s = 0.f;
#pragma unroll
            for (int ww = 0; ww < NW; ++ww) s += sred[ww];
            g_part[it] = s;
        }
    }

    // last-block final reduction (fixed order -> deterministic)
    __syncthreads();
    if (tid == 0) {
        __threadfence();
        unsigned d = atomicAdd(&g_done, 1u);
        s_item = (d == gridDim.x - 1) ? 1u : 0u;
    }
    __syncthreads();
    if (s_item) {
        __threadfence();
        float v = 0.f;
        for (int i = tid; i < NITEMS; i += BLK) v += g_part[i];
        sbest[tid] = v;
        __syncthreads();
#pragma unroll
        for (int st = BLK / 2; st > 0; st >>= 1) {
            if (tid < st) sbest[tid] += sbest[tid + st];
            __syncthreads();
        }
        if (tid == 0) {
            out[0] = sbest[0] * inv;
            g_ctr  = 0;
            g_done = 0;
        }
    }
}

extern "C" void kernel_launch(void* const* d_in, const int* in_sizes, int n_in,
                              void* d_out, int out_size) {
    const float* pred = (const float*)d_in[0];
    const float* tgt  = (const float*)d_in[1];
    const float* w    = (const float*)d_in[2];
    const float* pts  = (const float*)d_in[3];
    const float* sym  = (const float*)d_in[4];

    int C = in_sizes[4];
    int B = in_sizes[0] / (4 * C);
    int P = in_sizes[3] / (3 * C);
    int CHUNKS = (P + CHUNK - 1) / CHUNK;
    int NITEMS = B * CHUNKS;

    pm_fused<<<NBLOCKS, BLK>>>(pred, tgt, w, sym, pts,
                               B, C, P, CHUNKS, NITEMS,
                               1.f / (float)(B * P), (float*)d_out);
}

// round 5
// speedup vs baseline: 1.8470x; 1.0087x over previous
#include <cuda_runtime.h>
#include <math.h>

#define BLK      256
#define NW       8          // warps per block
#define CHUNK    128        // pred points per item
#define MAX_P    2048
#define NBLOCKS  456
#define MAX_ITEMS 4096

// cos(7.5 degrees): ang > 15deg  <=>  |dot| < cos(7.5deg)
#define COS_HALF_HARD 0.9914448613738104f

__device__ unsigned g_ctr  = 0;
__device__ unsigned g_done = 0;
__device__ float    g_part[MAX_ITEMS];

__device__ __forceinline__ float sl1(float v) {
    float a = fabsf(v);
    return (a < 1.f) ? 0.5f * v * v : a - 0.5f;
}

__device__ __forceinline__ void quat2rot(float w, float x, float y, float z, float* R) {
    R[0] = 1.f - 2.f * (y * y + z * z);
    R[1] = 2.f * (x * y - z * w);
    R[2] = 2.f * (x * z + y * w);
    R[3] = 2.f * (x * y + z * w);
    R[4] = 1.f - 2.f * (x * x + z * z);
    R[5] = 2.f * (y * z - x * w);
    R[6] = 2.f * (x * z - y * w);
    R[7] = 2.f * (y * z + x * w);
    R[8] = 1.f - 2.f * (x * x + y * y);
}

// Blackwell packed f32x2 FMA (SASS FFMA2) — only reachable via PTX.
__device__ __forceinline__ unsigned long long ffma2(unsigned long long a,
                                                    unsigned long long b,
                                                    unsigned long long c) {
    unsigned long long d;
    asm("fma.rn.f32x2 %0, %1, %2, %3;" : "=l"(d) : "l"(a), "l"(b), "l"(c));
    return d;
}

__device__ __forceinline__ unsigned long long pack2(float lo, float hi) {
    unsigned long long d;
    asm("mov.b64 %0, {%1, %2};" : "=l"(d)
        : "r"(__float_as_uint(lo)), "r"(__float_as_uint(hi)));
    return d;
}

__device__ __forceinline__ void unpack2(unsigned long long v,
                                        unsigned& lo, unsigned& hi) {
    asm("mov.b64 {%0, %1}, %2;" : "=r"(lo), "=r"(hi) : "l"(v));
}

__global__ void __launch_bounds__(BLK, 3)
pm_fused(const float* __restrict__ pred,
         const float* __restrict__ tgt,
         const float* __restrict__ w,
         const float* __restrict__ sym,
         const float* __restrict__ points,
         int B, int C, int P, int CHUNKS, int NITEMS,
         float inv, float* __restrict__ out) {
    // pair-transposed gt cloud: sg2[2i]   = {gx_q0, gx_q1, gy_q0, gy_q1}
    //                           sg2[2i+1] = {gz_q0, gz_q1, hw_q0, hw_q1}   (q0=2i)
    __shared__ float4   sg2[MAX_P];
    __shared__ float    sbest[NW * CHUNK];   // per-warp packed argmin partials
    __shared__ float    sred[NW];
    __shared__ unsigned s_item;

    const int tid  = threadIdx.x;
    const int wid  = tid >> 5;
    const int lane = tid & 31;

    int   prev_b = -1;   // sample whose setup is in registers
    int   fill_b = -1;   // sample whose gt cloud is in SMEM
    float Rp[9], Rg[9];
    int   cls = 0, valid = 0, use_closest = 0;

    const int HALF = (P + 1) >> 1;           // q-pairs
    const int PPW  = (HALF + NW - 1) / NW;   // q-pairs per warp

    for (;;) {
        if (tid == 0) s_item = atomicAdd(&g_ctr, 1u);
        __syncthreads();                     // claim barrier; protects sg2/sbest reuse
        unsigned it = s_item;
        if (it >= (unsigned)NITEMS) break;

        const int b     = (int)(it / (unsigned)CHUNKS);
        const int chunk = (int)(it % (unsigned)CHUNKS);

        if (b != prev_b) {                   // uniform across block
            prev_b = b;
            cls = 0; valid = 0;
            for (int c = 0; c < C; ++c) {
                if (__ldg(&w[(size_t)(b * C + c) * 4]) > 0.f) { cls = c; valid = 1; break; }
            }
            const float* qp = pred + (size_t)(b * C + cls) * 4;
            const float* qg = tgt  + (size_t)(b * C + cls) * 4;
            float pw = __ldg(qp + 0), px_ = __ldg(qp + 1), py_ = __ldg(qp + 2), pz_ = __ldg(qp + 3);
            float gw = __ldg(qg + 0), gx_ = __ldg(qg + 1), gy_ = __ldg(qg + 2), gz_ = __ldg(qg + 3);
            quat2rot(pw, px_, py_, pz_, Rp);
            quat2rot(gw, gx_, gy_, gz_, Rg);
            float dot = fabsf(pw * gw + px_ * gx_ + py_ * gy_ + pz_ * gz_);
            use_closest = (__ldg(&sym[cls]) > 0.f) && (dot < COS_HALF_HARD);
        }

        float lsum = 0.f;

        if (valid) {
            const float* pt    = points + (size_t)cls * P * 3;
            const int    pbase = chunk * CHUNK;

            if (use_closest) {
                // --- rotate + broadcast-pack this lane's 4 pred points ---
                unsigned long long npxx[4], npyy[4], npzz[4];
#pragma unroll
                for (int j = 0; j < 4; ++j) {
                    int p = pbase + lane + 32 * j;
                    float ppx = 0.f, ppy = 0.f, ppz = 0.f;
                    if (p < P) {
                        float x = __ldg(&pt[3 * p + 0]);
                        float y = __ldg(&pt[3 * p + 1]);
                        float z = __ldg(&pt[3 * p + 2]);
                        ppx = Rp[0] * x + Rp[1] * y + Rp[2] * z;
                        ppy = Rp[3] * x + Rp[4] * y + Rp[5] * z;
                        ppz = Rp[6] * x + Rp[7] * y + Rp[8] * z;
                    }
                    npxx[j] = pack2(-ppx, -ppx);
                    npyy[j] = pack2(-ppy, -ppy);
                    npzz[j] = pack2(-ppz, -ppz);
                }

                // --- fill pair-transposed gt cloud ---
                if (fill_b != b) {
                    for (int i = tid; i < HALF; i += BLK) {
                        int q0 = 2 * i, q1 = 2 * i + 1;
                        float x0 = __ldg(&pt[3 * q0 + 0]);
                        float y0 = __ldg(&pt[3 * q0 + 1]);
                        float z0 = __ldg(&pt[3 * q0 + 2]);
                        float g0x = Rg[0] * x0 + Rg[1] * y0 + Rg[2] * z0;
                        float g0y = Rg[3] * x0 + Rg[4] * y0 + Rg[5] * z0;
                        float g0z = Rg[6] * x0 + Rg[7] * y0 + Rg[8] * z0;
                        float h0  = 0.5f * (g0x * g0x + g0y * g0y + g0z * g0z);
                        float g1x = 0.f, g1y = 0.f, g1z = 0.f, h1 = 3.0e38f;
                        if (q1 < P) {
                            float x1 = __ldg(&pt[3 * q1 + 0]);
                            float y1 = __ldg(&pt[3 * q1 + 1]);
                            float z1 = __ldg(&pt[3 * q1 + 2]);
                            g1x = Rg[0] * x1 + Rg[1] * y1 + Rg[2] * z1;
                            g1y = Rg[3] * x1 + Rg[4] * y1 + Rg[5] * z1;
                            g1z = Rg[6] * x1 + Rg[7] * y1 + Rg[8] * z1;
                            h1  = 0.5f * (g1x * g1x + g1y * g1y + g1z * g1z);
                        }
                        sg2[2 * i]     = make_float4(g0x, g1x, g0y, g1y);
                        sg2[2 * i + 1] = make_float4(g0z, g1z, h0, h1);
                    }
                    fill_b = b;
                }
                __syncthreads();

                // --- warp scans its q-pair slice; 4 independent fmin chains ---
                // per pair-of-q: exact cross-half FMNMX, then 10-bit pair index
                // packed into masked mantissa, then chain FMNMX. 3 alu / 2 pairs.
                float best[4];
#pragma unroll
                for (int j = 0; j < 4; ++j) best[j] = __uint_as_float(0x7F7FFFFFu);

                const ulonglong2* sgu = reinterpret_cast<const ulonglong2*>(sg2);
                const int i0 = wid * PPW;
                const int i1 = min(i0 + PPW, HALF);
#pragma unroll 2
                for (int i = i0; i < i1; ++i) {
                    ulonglong2 va = sgu[2 * i];       // {gx0,gx1},{gy0,gy1}
                    ulonglong2 vb = sgu[2 * i + 1];   // {gz0,gz1},{h0,h1}
#pragma unroll
                    for (int j = 0; j < 4; ++j) {
                        unsigned long long t2 = ffma2(npzz[j], vb.x, vb.y);
                        t2 = ffma2(npyy[j], va.y, t2);
                        t2 = ffma2(npxx[j], va.x, t2);
                        unsigned tlo, thi;
                        unpack2(t2, tlo, thi);
                        float m2 = fminf(__uint_as_float(tlo), __uint_as_float(thi));
                        unsigned km = (__float_as_uint(m2) & 0xFFFFFC00u) | (unsigned)i;
                        best[j] = fminf(best[j], __uint_as_float(km));
                    }
                }
#pragma unroll
                for (int j = 0; j < 4; ++j)
                    sbest[wid * CHUNK + lane + 32 * j] = best[j];
                __syncthreads();

                // --- thread t (<128) finalizes pred point pbase+t ---
                if (tid < CHUNK) {
                    int p = pbase + tid;
                    if (p < P) {
                        float m = sbest[tid];
#pragma unroll
                        for (int ww = 1; ww < NW; ++ww)
                            m = fminf(m, sbest[ww * CHUNK + tid]);
                        int k = (int)(__float_as_uint(m) & 0x3FFu);   // pair index

                        float x = __ldg(&pt[3 * p + 0]);
                        float y = __ldg(&pt[3 * p + 1]);
                        float z = __ldg(&pt[3 * p + 2]);
                        float ppx = Rp[0] * x + Rp[1] * y + Rp[2] * z;
                        float ppy = Rp[3] * x + Rp[4] * y + Rp[5] * z;
                        float ppz = Rp[6] * x + Rp[7] * y + Rp[8] * z;

                        float4 A  = sg2[2 * k];
                        float4 Bv = sg2[2 * k + 1];
                        // recompute both t's bit-identically to the FFMA2 path
                        float t0 = fmaf(-ppx, A.x, fmaf(-ppy, A.z, fmaf(-ppz, Bv.x, Bv.z)));
                        float t1 = fmaf(-ppx, A.y, fmaf(-ppy, A.w, fmaf(-ppz, Bv.y, Bv.w)));
                        float gx, gy, gz;
                        if (t1 < t0) { gx = A.y; gy = A.w; gz = Bv.y; }
                        else         { gx = A.x; gy = A.z; gz = Bv.x; }
                        lsum = sl1(ppx - gx) + sl1(ppy - gy) + sl1(ppz - gz);
                    }
                }
            } else {
                if (tid < CHUNK) {
                    int p = pbase + tid;
                    if (p < P) {
                        float x = __ldg(&pt[3 * p + 0]);
                        float y = __ldg(&pt[3 * p + 1]);
                        float z = __ldg(&pt[3 * p + 2]);
                        float ppx = Rp[0] * x + Rp[1] * y + Rp[2] * z;
                        float ppy = Rp[3] * x + Rp[4] * y + Rp[5] * z;
                        float ppz = Rp[6] * x + Rp[7] * y + Rp[8] * z;
                        float gx = Rg[0] * x + Rg[1] * y + Rg[2] * z;
                        float gy = Rg[3] * x + Rg[4] * y + Rg[5] * z;
                        float gz = Rg[6] * x + Rg[7] * y + Rg[8] * z;
                        lsum = sl1(ppx - gx) + sl1(ppy - gy) + sl1(ppz - gz);
                    }
                }
            }
        }

        // deterministic per-item reduce (shuffle tree + fixed-order warp merge)
#pragma unroll
        for (int off = 16; off > 0; off >>= 1)
            lsum += __shfl_down_sync(0xFFFFFFFFu, lsum, off);
        if (lane == 0) sred[wid] = lsum;
        __syncthreads();
        if (tid == 0) {
            float s = 0.f;
#pragma unroll
            for (int ww = 0; ww < NW; ++ww) s += sred[ww];
            g_part[it] = s;
        }
    }

    // last-block final reduction (fixed order -> deterministic)
    __syncthreads();
    if (tid == 0) {
        __threadfence();
        unsigned d = atomicAdd(&g_done, 1u);
        s_item = (d == gridDim.x - 1) ? 1u : 0u;
    }
    __syncthreads();
    if (s_item) {
        __threadfence();
        float v = 0.f;
        for (int i = tid; i < NITEMS; i += BLK) v += g_part[i];
        sbest[tid] = v;
        __syncthreads();
#pragma unroll
        for (int st = BLK / 2; st > 0; st >>= 1) {
            if (tid < st) sbest[tid] += sbest[tid + st];
            __syncthreads();
        }
        if (tid == 0) {
            out[0] = sbest[0] * inv;
            g_ctr  = 0;
            g_done = 0;
        }
    }
}

extern "C" void kernel_launch(void* const* d_in, const int* in_sizes, int n_in,
                              void* d_out, int out_size) {
    const float* pred = (const float*)d_in[0];
    const float* tgt  = (const float*)d_in[1];
    const float* w    = (const float*)d_in[2];
    const float* pts  = (const float*)d_in[3];
    const float* sym  = (const float*)d_in[4];

    int C = in_sizes[4];
    int B = in_sizes[0] / (4 * C);
    int P = in_sizes[3] / (3 * C);
    int CHUNKS = (P + CHUNK - 1) / CHUNK;
    int NITEMS = B * CHUNKS;

    pm_fused<<<NBLOCKS, BLK>>>(pred, tgt, w, sym, pts,
                               B, C, P, CHUNKS, NITEMS,
                               1.f / (float)(B * P), (float*)d_out);
}